// round 2
// baseline (speedup 1.0000x reference)
#include <cuda_runtime.h>
#include <math.h>

#define NN 100000
#define DD 128
#define HH 16
#define EE 1600000
#define BB 16384

// ---------------- scratch (device globals; no allocations allowed) ----------
__device__ float g_deg [NN];
__device__ float g_y1  [NN * HH];   // x @ w1_l
__device__ float g_z1  [NN * HH];   // x @ w1_r
__device__ float g_agg [NN * HH];   // segsum(y1[src]) by dst
__device__ float g_h   [NN * HH];   // layer-1 output
__device__ float g_aggh[NN * HH];   // segsum(h[src]) by dst
__device__ float g_s1  [NN];
__device__ float g_s2  [NN];
__device__ float g_u   [66];        // u_l_a[16], u_r_a[16], u_l_b[16], u_r_b[16], c_a, c_b
__device__ float g_partial[64];

// vector f32 reduction (sm_90+): 4 floats in one L2 atomic op
__device__ __forceinline__ void red4(float* p, float4 v) {
    asm volatile("red.global.add.v4.f32 [%0], {%1, %2, %3, %4};"
                 :: "l"(p), "f"(v.x), "f"(v.y), "f"(v.z), "f"(v.w) : "memory");
}

// ---------------- K0: zero scratch --------------------------------------
__global__ void k_zero() {
    int idx = blockIdx.x * blockDim.x + threadIdx.x;
    int stride = gridDim.x * blockDim.x;
    const int n4 = NN * HH / 4;  // 400000 float4 per agg buffer
    float4 z4 = make_float4(0.f, 0.f, 0.f, 0.f);
    for (int i = idx; i < n4; i += stride) {
        reinterpret_cast<float4*>(g_agg)[i]  = z4;
        reinterpret_cast<float4*>(g_aggh)[i] = z4;
    }
    for (int i = idx; i < NN; i += stride) g_deg[i] = 0.f;
}

// ---------------- K1: in-degree ------------------------------------------
__global__ void k_deg(const int* __restrict__ dst) {
    int idx = blockIdx.x * blockDim.x + threadIdx.x;   // EE/4 threads
    if (idx >= EE / 4) return;
    int4 d = reinterpret_cast<const int4*>(dst)[idx];
    atomicAdd(&g_deg[d.x], 1.f);
    atomicAdd(&g_deg[d.y], 1.f);
    atomicAdd(&g_deg[d.z], 1.f);
    atomicAdd(&g_deg[d.w], 1.f);
}

// ---------------- K2: proj  y1 = x@w1_l, z1 = x@w1_r ----------------------
// block: 256 threads, 128 rows, 32 outputs, register tile 4 rows x 4 outs.
__global__ void k_proj(const float* __restrict__ x,
                       const float* __restrict__ w1l,
                       const float* __restrict__ w1r) {
    __shared__ float sw[DD * 32];        // sw[k*32 + j]: j<16 from w1l, else w1r
    __shared__ float sxT[32 * 132];      // transposed x chunk: [kk][row], pad 132

    const int tid = threadIdx.x;
    // stage weights (once)
    for (int i = tid; i < DD * 32; i += 256) {
        int k = i >> 5, j = i & 31;
        sw[i] = (j < 16) ? w1l[k * HH + j] : w1r[k * HH + (j - 16)];
    }

    const int row0 = blockIdx.x * 128;
    const int rq = tid >> 3;   // 0..31 -> rows rq*4..rq*4+3
    const int g  = tid & 7;    // 0..7  -> outs g*4..g*4+3

    float acc[4][4];
#pragma unroll
    for (int i = 0; i < 4; i++)
#pragma unroll
        for (int j = 0; j < 4; j++) acc[i][j] = 0.f;

    const int rs = tid >> 3;   // staging: row within pass (0..31)
    const int q  = tid & 7;    // staging: float4 index within 128B row-chunk

    for (int kc = 0; kc < 4; kc++) {
        __syncthreads();
        // stage 128 rows x 32 k-cols, transposed into sxT
#pragma unroll
        for (int rr = rs; rr < 128; rr += 32) {
            int row = row0 + rr;
            float4 v = make_float4(0.f, 0.f, 0.f, 0.f);
            if (row < NN)
                v = reinterpret_cast<const float4*>(x + row * DD + kc * 32)[q];
            sxT[(q * 4 + 0) * 132 + rr] = v.x;
            sxT[(q * 4 + 1) * 132 + rr] = v.y;
            sxT[(q * 4 + 2) * 132 + rr] = v.z;
            sxT[(q * 4 + 3) * 132 + rr] = v.w;
        }
        __syncthreads();
#pragma unroll
        for (int kk = 0; kk < 32; kk++) {
            float4 xv = *reinterpret_cast<const float4*>(&sxT[kk * 132 + rq * 4]);
            float4 wv = *reinterpret_cast<const float4*>(&sw[(kc * 32 + kk) * 32 + g * 4]);
            acc[0][0] += xv.x * wv.x; acc[0][1] += xv.x * wv.y; acc[0][2] += xv.x * wv.z; acc[0][3] += xv.x * wv.w;
            acc[1][0] += xv.y * wv.x; acc[1][1] += xv.y * wv.y; acc[1][2] += xv.y * wv.z; acc[1][3] += xv.y * wv.w;
            acc[2][0] += xv.z * wv.x; acc[2][1] += xv.z * wv.y; acc[2][2] += xv.z * wv.z; acc[2][3] += xv.z * wv.w;
            acc[3][0] += xv.w * wv.x; acc[3][1] += xv.w * wv.y; acc[3][2] += xv.w * wv.z; acc[3][3] += xv.w * wv.w;
        }
    }

#pragma unroll
    for (int i = 0; i < 4; i++) {
        int row = row0 + rq * 4 + i;
        if (row < NN) {
            float4 v = make_float4(acc[i][0], acc[i][1], acc[i][2], acc[i][3]);
            if (g < 4) reinterpret_cast<float4*>(g_y1 + row * HH)[g]     = v;
            else       reinterpret_cast<float4*>(g_z1 + row * HH)[g - 4] = v;
        }
    }
}

// ---------------- K3: edge aggregation layer 1 (y1 -> agg) ----------------
// NOTE: device globals referenced INSIDE device code (host-passed __device__
// symbol pointers resolve to the host shadow and silently read zeros via ATS).
__global__ void k_agg1(const int* __restrict__ src, const int* __restrict__ dst) {
    int e = blockIdx.x * blockDim.x + threadIdx.x;
    if (e >= EE) return;
    int s = src[e], d = dst[e];
    const float4* ip = reinterpret_cast<const float4*>(g_y1 + (long)s * HH);
    float4 a = ip[0], b = ip[1], c = ip[2], f = ip[3];
    float* op = g_agg + (long)d * HH;
    red4(op + 0,  a);
    red4(op + 4,  b);
    red4(op + 8,  c);
    red4(op + 12, f);
}

// ---------------- K5: edge aggregation layer 2 (h -> aggh) ----------------
__global__ void k_agg2(const int* __restrict__ src, const int* __restrict__ dst) {
    int e = blockIdx.x * blockDim.x + threadIdx.x;
    if (e >= EE) return;
    int s = src[e], d = dst[e];
    const float4* ip = reinterpret_cast<const float4*>(g_h + (long)s * HH);
    float4 a = ip[0], b = ip[1], c = ip[2], f = ip[3];
    float* op = g_aggh + (long)d * HH;
    red4(op + 0,  a);
    red4(op + 4,  b);
    red4(op + 8,  c);
    red4(op + 12, f);
}

// ---------------- K4: h = relu(agg*invdeg + b1 + z1) ----------------------
__global__ void k_h(const float* __restrict__ b1) {
    int idx = blockIdx.x * blockDim.x + threadIdx.x;   // NN*4 float4s
    if (idx >= NN * 4) return;
    int n = idx >> 2, j4 = idx & 3;
    float inv = 1.f / fmaxf(g_deg[n], 1.f);
    float4 a = reinterpret_cast<const float4*>(g_agg)[idx];
    float4 z = reinterpret_cast<const float4*>(g_z1)[idx];
    float4 bv = reinterpret_cast<const float4*>(b1)[j4];
    float4 h;
    h.x = fmaxf(a.x * inv + bv.x + z.x, 0.f);
    h.y = fmaxf(a.y * inv + bv.y + z.y, 0.f);
    h.z = fmaxf(a.z * inv + bv.z + z.z, 0.f);
    h.w = fmaxf(a.w * inv + bv.w + z.w, 0.f);
    reinterpret_cast<float4*>(g_h)[idx] = h;
}

// ---------------- K6: collapse layer-2 weights against wc -----------------
__global__ void k_prep(const float* __restrict__ w2l, const float* __restrict__ w2r,
                       const float* __restrict__ b2,  const float* __restrict__ wc) {
    int t = threadIdx.x;           // 64 threads
    if (t < 64) {
        int which = t >> 4, j = t & 15;
        const float* w = (which == 0 || which == 2) ? w2l : w2r;
        const float* c = (which < 2) ? wc : (wc + DD);
        float s = 0.f;
        for (int d = 0; d < DD; d++) s += w[j * DD + d] * c[d];
        g_u[which * 16 + j] = s;
    }
    if (t == 0) { float s = 0.f; for (int d = 0; d < DD; d++) s += b2[d] * wc[d];      g_u[64] = s; }
    if (t == 1) { float s = 0.f; for (int d = 0; d < DD; d++) s += b2[d] * wc[DD + d]; g_u[65] = s; }
}

// ---------------- K7: per-node classifier scalars -------------------------
__global__ void k_s() {
    __shared__ float su[66];
    if (threadIdx.x < 66) su[threadIdx.x] = g_u[threadIdx.x];
    __syncthreads();
    int n = blockIdx.x * blockDim.x + threadIdx.x;
    if (n >= NN) return;
    float inv = 1.f / fmaxf(g_deg[n], 1.f);
    float s1 = su[64], s2 = su[65];
#pragma unroll
    for (int j4 = 0; j4 < 4; j4++) {
        float4 a = reinterpret_cast<const float4*>(g_aggh + (long)n * HH)[j4];
        float4 h = reinterpret_cast<const float4*>(g_h    + (long)n * HH)[j4];
        int j = j4 * 4;
        float ax = a.x * inv, ay = a.y * inv, az = a.z * inv, aw = a.w * inv;
        s1 += ax * su[j] + ay * su[j + 1] + az * su[j + 2] + aw * su[j + 3];
        s1 += h.x * su[16 + j] + h.y * su[17 + j] + h.z * su[18 + j] + h.w * su[19 + j];
        s2 += ax * su[32 + j] + ay * su[33 + j] + az * su[34 + j] + aw * su[35 + j];
        s2 += h.x * su[48 + j] + h.y * su[49 + j] + h.z * su[50 + j] + h.w * su[51 + j];
    }
    g_s1[n] = s1;
    g_s2[n] = s2;
}

// ---------------- K8: logits + partial BCE --------------------------------
__global__ void k_loss(const int* __restrict__ a1, const int* __restrict__ a2,
                       const int* __restrict__ labels, const float* __restrict__ bc,
                       float* __restrict__ out) {
    int tid = threadIdx.x;
    float acc = 0.f;
    float bias = bc[0];
    for (int i = blockIdx.x * 256 + tid; i < BB; i += 64 * 256) {
        float l = g_s1[a1[i]] + g_s2[a2[i]] + bias;
        out[1 + i] = l;
        float y = (float)labels[i];
        acc += fmaxf(l, 0.f) - l * y + log1pf(expf(-fabsf(l)));
    }
    __shared__ float sred[256];
    sred[tid] = acc;
    __syncthreads();
    for (int s = 128; s > 0; s >>= 1) {
        if (tid < s) sred[tid] += sred[tid + s];
        __syncthreads();
    }
    if (tid == 0) g_partial[blockIdx.x] = sred[0];
}

// ---------------- K9: final loss reduce -----------------------------------
__global__ void k_final(float* __restrict__ out) {
    __shared__ float sred[64];
    int t = threadIdx.x;
    sred[t] = g_partial[t];
    __syncthreads();
    for (int s = 32; s > 0; s >>= 1) {
        if (t < s) sred[t] += sred[t + s];
        __syncthreads();
    }
    if (t == 0) out[0] = sred[0] * (1.f / (float)BB);
}

// ---------------- launch ---------------------------------------------------
extern "C" void kernel_launch(void* const* d_in, const int* in_sizes, int n_in,
                              void* d_out, int out_size) {
    const float* x    = (const float*)d_in[0];
    const float* w1l  = (const float*)d_in[1];
    const float* b1   = (const float*)d_in[2];
    const float* w1r  = (const float*)d_in[3];
    const float* w2l  = (const float*)d_in[4];
    const float* b2   = (const float*)d_in[5];
    const float* w2r  = (const float*)d_in[6];
    const float* wc   = (const float*)d_in[7];
    const float* bc   = (const float*)d_in[8];
    const int*   edge = (const int*)d_in[9];
    const int*   a1   = (const int*)d_in[10];
    const int*   a2   = (const int*)d_in[11];
    const int*   lab  = (const int*)d_in[12];
    float* out = (float*)d_out;

    const int* src = edge;
    const int* dst = edge + EE;

    k_zero<<<2048, 256>>>();
    k_deg <<<(EE / 4 + 255) / 256, 256>>>(dst);
    k_proj<<<(NN + 127) / 128, 256>>>(x, w1l, w1r);
    k_agg1<<<(EE + 255) / 256, 256>>>(src, dst);
    k_h   <<<(NN * 4 + 255) / 256, 256>>>(b1);
    k_agg2<<<(EE + 255) / 256, 256>>>(src, dst);
    k_prep<<<1, 64>>>(w2l, w2r, b2, wc);
    k_s   <<<(NN + 255) / 256, 256>>>();
    k_loss<<<64, 256>>>(a1, a2, lab, bc, out);
    k_final<<<1, 64>>>(out);
}

// round 3
// speedup vs baseline: 1.3282x; 1.3282x over previous
#include <cuda_runtime.h>
#include <math.h>

#define NN 100000
#define DD 128
#define HH 16
#define EE 1600000
#define BB 16384

// ---------------- scratch (device globals; no allocations allowed) ----------
__device__ float g_deg [NN];
__device__ float g_y1  [NN * HH];   // x @ w1_l
__device__ float g_z1  [NN * HH];   // x @ w1_r
__device__ float g_agg [NN * HH];   // segsum(y1[src]) by dst
__device__ float2 g_p  [NN];        // (dot(h,u_l_a), dot(h,u_l_b)) per node
__device__ float2 g_q  [NN];        // (dot(h,u_r_a), dot(h,u_r_b)) per node
__device__ float2 g_ap [NN];        // segsum of g_p over edges
__device__ float g_s1  [NN];
__device__ float g_s2  [NN];
__device__ float g_u   [66];        // u_l_a[16], u_r_a[16], u_l_b[16], u_r_b[16], c_a, c_b
__device__ float g_partial[64];

// vector f32 reductions (sm_90+): one L2 atomic op
__device__ __forceinline__ void red4(float* p, float4 v) {
    asm volatile("red.global.add.v4.f32 [%0], {%1, %2, %3, %4};"
                 :: "l"(p), "f"(v.x), "f"(v.y), "f"(v.z), "f"(v.w) : "memory");
}
__device__ __forceinline__ void red2(float* p, float2 v) {
    asm volatile("red.global.add.v2.f32 [%0], {%1, %2};"
                 :: "l"(p), "f"(v.x), "f"(v.y) : "memory");
}
__device__ __forceinline__ void red1(float* p, float v) {
    asm volatile("red.global.add.f32 [%0], %1;" :: "l"(p), "f"(v) : "memory");
}

// ---------------- K0: zero scratch --------------------------------------
__global__ void k_zero() {
    int idx = blockIdx.x * blockDim.x + threadIdx.x;
    int stride = gridDim.x * blockDim.x;
    const int n4 = NN * HH / 4;
    float4 z4 = make_float4(0.f, 0.f, 0.f, 0.f);
    for (int i = idx; i < n4; i += stride)
        reinterpret_cast<float4*>(g_agg)[i] = z4;
    float2 z2 = make_float2(0.f, 0.f);
    for (int i = idx; i < NN; i += stride) {
        g_ap[i] = z2;
        g_deg[i] = 0.f;
    }
}

// ---------------- K2: proj  y1 = x@w1_l, z1 = x@w1_r ----------------------
__global__ void k_proj(const float* __restrict__ x,
                       const float* __restrict__ w1l,
                       const float* __restrict__ w1r) {
    __shared__ float sw[DD * 32];        // sw[k*32 + j]: j<16 from w1l, else w1r
    __shared__ float sxT[32 * 132];      // transposed x chunk: [kk][row], pad 132

    const int tid = threadIdx.x;
    for (int i = tid; i < DD * 32; i += 256) {
        int k = i >> 5, j = i & 31;
        sw[i] = (j < 16) ? w1l[k * HH + j] : w1r[k * HH + (j - 16)];
    }

    const int row0 = blockIdx.x * 128;
    const int rq = tid >> 3;
    const int g  = tid & 7;

    float acc[4][4];
#pragma unroll
    for (int i = 0; i < 4; i++)
#pragma unroll
        for (int j = 0; j < 4; j++) acc[i][j] = 0.f;

    const int rs = tid >> 3;
    const int q  = tid & 7;

    for (int kc = 0; kc < 4; kc++) {
        __syncthreads();
#pragma unroll
        for (int rr = rs; rr < 128; rr += 32) {
            int row = row0 + rr;
            float4 v = make_float4(0.f, 0.f, 0.f, 0.f);
            if (row < NN)
                v = reinterpret_cast<const float4*>(x + row * DD + kc * 32)[q];
            sxT[(q * 4 + 0) * 132 + rr] = v.x;
            sxT[(q * 4 + 1) * 132 + rr] = v.y;
            sxT[(q * 4 + 2) * 132 + rr] = v.z;
            sxT[(q * 4 + 3) * 132 + rr] = v.w;
        }
        __syncthreads();
#pragma unroll
        for (int kk = 0; kk < 32; kk++) {
            float4 xv = *reinterpret_cast<const float4*>(&sxT[kk * 132 + rq * 4]);
            float4 wv = *reinterpret_cast<const float4*>(&sw[(kc * 32 + kk) * 32 + g * 4]);
            acc[0][0] += xv.x * wv.x; acc[0][1] += xv.x * wv.y; acc[0][2] += xv.x * wv.z; acc[0][3] += xv.x * wv.w;
            acc[1][0] += xv.y * wv.x; acc[1][1] += xv.y * wv.y; acc[1][2] += xv.y * wv.z; acc[1][3] += xv.y * wv.w;
            acc[2][0] += xv.z * wv.x; acc[2][1] += xv.z * wv.y; acc[2][2] += xv.z * wv.z; acc[2][3] += xv.z * wv.w;
            acc[3][0] += xv.w * wv.x; acc[3][1] += xv.w * wv.y; acc[3][2] += xv.w * wv.z; acc[3][3] += xv.w * wv.w;
        }
    }

#pragma unroll
    for (int i = 0; i < 4; i++) {
        int row = row0 + rq * 4 + i;
        if (row < NN) {
            float4 v = make_float4(acc[i][0], acc[i][1], acc[i][2], acc[i][3]);
            if (g < 4) reinterpret_cast<float4*>(g_y1 + row * HH)[g]     = v;
            else       reinterpret_cast<float4*>(g_z1 + row * HH)[g - 4] = v;
        }
    }
}

// ---------------- K3: edge aggregation layer 1 (y1 -> agg) + degree -------
__global__ void k_agg1(const int* __restrict__ src, const int* __restrict__ dst) {
    int e = blockIdx.x * blockDim.x + threadIdx.x;
    if (e >= EE) return;
    int s = src[e], d = dst[e];
    const float4* ip = reinterpret_cast<const float4*>(g_y1 + (long)s * HH);
    float4 a = ip[0], b = ip[1], c = ip[2], f = ip[3];
    float* op = g_agg + (long)d * HH;
    red4(op + 0,  a);
    red4(op + 4,  b);
    red4(op + 8,  c);
    red4(op + 12, f);
    red1(&g_deg[d], 1.f);
}

// ---------------- K6: collapse layer-2 weights against wc -----------------
__global__ void k_prep(const float* __restrict__ w2l, const float* __restrict__ w2r,
                       const float* __restrict__ b2,  const float* __restrict__ wc) {
    int t = threadIdx.x;           // 64 threads
    if (t < 64) {
        int which = t >> 4, j = t & 15;
        const float* w = (which == 0 || which == 2) ? w2l : w2r;
        const float* c = (which < 2) ? wc : (wc + DD);
        float s = 0.f;
        for (int d = 0; d < DD; d++) s += w[j * DD + d] * c[d];
        g_u[which * 16 + j] = s;
    }
    if (t == 0) { float s = 0.f; for (int d = 0; d < DD; d++) s += b2[d] * wc[d];      g_u[64] = s; }
    if (t == 1) { float s = 0.f; for (int d = 0; d < DD; d++) s += b2[d] * wc[DD + d]; g_u[65] = s; }
}

// ---------------- K4: h = relu(agg*invdeg + b1 + z1); contract to p,q -----
// p = (h.u_l_a, h.u_l_b)  -> to be aggregated over edges
// q = (h.u_r_a, h.u_r_b)  -> self term
__global__ void k_h(const float* __restrict__ b1) {
    __shared__ float su[64];
    __shared__ float sb[16];
    if (threadIdx.x < 64) su[threadIdx.x] = g_u[threadIdx.x];
    if (threadIdx.x < 16) sb[threadIdx.x] = b1[threadIdx.x];
    __syncthreads();
    int n = blockIdx.x * blockDim.x + threadIdx.x;
    if (n >= NN) return;
    float inv = 1.f / fmaxf(g_deg[n], 1.f);
    float p1 = 0.f, p2 = 0.f, q1 = 0.f, q2 = 0.f;
#pragma unroll
    for (int j4 = 0; j4 < 4; j4++) {
        float4 a = reinterpret_cast<const float4*>(g_agg + (long)n * HH)[j4];
        float4 z = reinterpret_cast<const float4*>(g_z1  + (long)n * HH)[j4];
        int j = j4 * 4;
        float h0 = fmaxf(a.x * inv + sb[j + 0] + z.x, 0.f);
        float h1 = fmaxf(a.y * inv + sb[j + 1] + z.y, 0.f);
        float h2 = fmaxf(a.z * inv + sb[j + 2] + z.z, 0.f);
        float h3 = fmaxf(a.w * inv + sb[j + 3] + z.w, 0.f);
        p1 += h0 * su[j]      + h1 * su[j + 1]  + h2 * su[j + 2]  + h3 * su[j + 3];
        q1 += h0 * su[16 + j] + h1 * su[17 + j] + h2 * su[18 + j] + h3 * su[19 + j];
        p2 += h0 * su[32 + j] + h1 * su[33 + j] + h2 * su[34 + j] + h3 * su[35 + j];
        q2 += h0 * su[48 + j] + h1 * su[49 + j] + h2 * su[50 + j] + h3 * su[51 + j];
    }
    g_p[n] = make_float2(p1, p2);
    g_q[n] = make_float2(q1, q2);
}

// ---------------- K5: edge aggregation layer 2 (p -> ap), 2 floats/edge ---
__global__ void k_agg2(const int* __restrict__ src, const int* __restrict__ dst) {
    int idx = blockIdx.x * blockDim.x + threadIdx.x;   // EE/4 threads
    if (idx >= EE / 4) return;
    int4 s = reinterpret_cast<const int4*>(src)[idx];
    int4 d = reinterpret_cast<const int4*>(dst)[idx];
    float2 v0 = g_p[s.x];
    float2 v1 = g_p[s.y];
    float2 v2 = g_p[s.z];
    float2 v3 = g_p[s.w];
    red2(reinterpret_cast<float*>(&g_ap[d.x]), v0);
    red2(reinterpret_cast<float*>(&g_ap[d.y]), v1);
    red2(reinterpret_cast<float*>(&g_ap[d.z]), v2);
    red2(reinterpret_cast<float*>(&g_ap[d.w]), v3);
}

// ---------------- K7: per-node classifier scalars -------------------------
__global__ void k_s() {
    int n = blockIdx.x * blockDim.x + threadIdx.x;
    if (n >= NN) return;
    float inv = 1.f / fmaxf(g_deg[n], 1.f);
    float2 ap = g_ap[n];
    float2 q  = g_q[n];
    g_s1[n] = ap.x * inv + q.x + g_u[64];
    g_s2[n] = ap.y * inv + q.y + g_u[65];
}

// ---------------- K8: logits + partial BCE --------------------------------
__global__ void k_loss(const int* __restrict__ a1, const int* __restrict__ a2,
                       const int* __restrict__ labels, const float* __restrict__ bc,
                       float* __restrict__ out) {
    int tid = threadIdx.x;
    float acc = 0.f;
    float bias = bc[0];
    for (int i = blockIdx.x * 256 + tid; i < BB; i += 64 * 256) {
        float l = g_s1[a1[i]] + g_s2[a2[i]] + bias;
        out[1 + i] = l;
        float y = (float)labels[i];
        acc += fmaxf(l, 0.f) - l * y + log1pf(expf(-fabsf(l)));
    }
    __shared__ float sred[256];
    sred[tid] = acc;
    __syncthreads();
    for (int s = 128; s > 0; s >>= 1) {
        if (tid < s) sred[tid] += sred[tid + s];
        __syncthreads();
    }
    if (tid == 0) g_partial[blockIdx.x] = sred[0];
}

// ---------------- K9: final loss reduce -----------------------------------
__global__ void k_final(float* __restrict__ out) {
    __shared__ float sred[64];
    int t = threadIdx.x;
    sred[t] = g_partial[t];
    __syncthreads();
    for (int s = 32; s > 0; s >>= 1) {
        if (t < s) sred[t] += sred[t + s];
        __syncthreads();
    }
    if (t == 0) out[0] = sred[0] * (1.f / (float)BB);
}

// ---------------- launch ---------------------------------------------------
extern "C" void kernel_launch(void* const* d_in, const int* in_sizes, int n_in,
                              void* d_out, int out_size) {
    const float* x    = (const float*)d_in[0];
    const float* w1l  = (const float*)d_in[1];
    const float* b1   = (const float*)d_in[2];
    const float* w1r  = (const float*)d_in[3];
    const float* w2l  = (const float*)d_in[4];
    const float* b2   = (const float*)d_in[5];
    const float* w2r  = (const float*)d_in[6];
    const float* wc   = (const float*)d_in[7];
    const float* bc   = (const float*)d_in[8];
    const int*   edge = (const int*)d_in[9];
    const int*   a1   = (const int*)d_in[10];
    const int*   a2   = (const int*)d_in[11];
    const int*   lab  = (const int*)d_in[12];
    float* out = (float*)d_out;

    const int* src = edge;
    const int* dst = edge + EE;

    k_zero<<<1024, 256>>>();
    k_prep<<<1, 64>>>(w2l, w2r, b2, wc);
    k_proj<<<(NN + 127) / 128, 256>>>(x, w1l, w1r);
    k_agg1<<<(EE + 255) / 256, 256>>>(src, dst);
    k_h   <<<(NN + 255) / 256, 256>>>(b1);
    k_agg2<<<(EE / 4 + 255) / 256, 256>>>(src, dst);
    k_s   <<<(NN + 255) / 256, 256>>>();
    k_loss<<<64, 256>>>(a1, a2, lab, bc, out);
    k_final<<<1, 64>>>(out);
}

// round 4
// speedup vs baseline: 1.3951x; 1.0503x over previous
#include <cuda_runtime.h>
#include <math.h>

#define NN 100000
#define DD 128
#define HH 16
#define EE 1600000
#define BB 16384
#define FULL 0xffffffffu

typedef unsigned long long u64;

// ---------------- scratch (device globals) ---------------------------------
__device__ int    g_degi[NN];       // in-degree (int)
__device__ int    g_incl[NN];       // block-local inclusive scan
__device__ int    g_bsum[128];      // per-block totals
__device__ int    g_boff[128];      // exclusive scan of block totals
__device__ int    g_row [NN + 1];   // CSR row offsets
__device__ int    g_cur [NN];       // fill cursors
__device__ float  g_inv [NN];       // 1/max(deg,1)
__device__ int    g_csr [EE];       // CSR adjacency (src per slot)
__device__ float  g_y1  [NN * HH];  // x @ w1_l
__device__ float  g_z1  [NN * HH];  // x @ w1_r
__device__ float2 g_p   [NN];       // (h.u_l_a, h.u_l_b)
__device__ float2 g_q   [NN];       // (h.u_r_a, h.u_r_b)
__device__ float  g_s1  [NN];
__device__ float  g_s2  [NN];
__device__ float  g_u   [66];
__device__ float  g_partial[64];

// f32x2 packed math (sm_100+)
#define PK(d, lo, hi)  asm("mov.b64 %0, {%1,%2};" : "=l"(d) : "f"(lo), "f"(hi))
#define UPK(lo, hi, s) asm("mov.b64 {%0,%1}, %2;" : "=f"(lo), "=f"(hi) : "l"(s))
#define FMA2(d, a, b)  asm("fma.rn.f32x2 %0, %1, %2, %0;" : "+l"(d) : "l"(a), "l"(b))

// ---------------- K0: zero degree counters ---------------------------------
__global__ void k_zero() {
    int n = blockIdx.x * blockDim.x + threadIdx.x;
    if (n < NN) g_degi[n] = 0;
}

// ---------------- K1: in-degree histogram ----------------------------------
__global__ void k_deg(const int* __restrict__ dst) {
    int idx = blockIdx.x * blockDim.x + threadIdx.x;
    if (idx >= EE / 4) return;
    int4 d = reinterpret_cast<const int4*>(dst)[idx];
    atomicAdd(&g_degi[d.x], 1);
    atomicAdd(&g_degi[d.y], 1);
    atomicAdd(&g_degi[d.z], 1);
    atomicAdd(&g_degi[d.w], 1);
}

// ---------------- scan A: 1024-wide block inclusive scan -------------------
__global__ void k_scanA() {
    __shared__ int ws[32];
    int tid = threadIdx.x, lane = tid & 31, w = tid >> 5;
    int n = blockIdx.x * 1024 + tid;
    int v = (n < NN) ? g_degi[n] : 0;
    int x = v;
#pragma unroll
    for (int o = 1; o < 32; o <<= 1) {
        int t = __shfl_up_sync(FULL, x, o);
        if (lane >= o) x += t;
    }
    if (lane == 31) ws[w] = x;
    __syncthreads();
    if (w == 0) {
        int b = ws[lane];
#pragma unroll
        for (int o = 1; o < 32; o <<= 1) {
            int t = __shfl_up_sync(FULL, b, o);
            if (lane >= o) b += t;
        }
        ws[lane] = b;
    }
    __syncthreads();
    int incl = x + (w > 0 ? ws[w - 1] : 0);
    if (n < NN) g_incl[n] = incl;
    if (tid == 1023) g_bsum[blockIdx.x] = incl;
}

// ---------------- scan B: exclusive scan of block totals -------------------
__global__ void k_scanB() {
    __shared__ int s[128];
    int tid = threadIdx.x;
    int v = (tid < 98) ? g_bsum[tid] : 0;
    s[tid] = v;
    __syncthreads();
    for (int o = 1; o < 128; o <<= 1) {
        int t = (tid >= o) ? s[tid - o] : 0;
        __syncthreads();
        s[tid] += t;
        __syncthreads();
    }
    if (tid < 98) g_boff[tid] = s[tid] - v;   // exclusive
    if (tid == 0) g_row[NN] = EE;
}

// ---------------- scan C: finalize row offsets, cursors, inv-deg -----------
__global__ void k_scanC() {
    int n = blockIdx.x * blockDim.x + threadIdx.x;
    if (n >= NN) return;
    int d = g_degi[n];
    int excl = g_incl[n] - d + g_boff[n >> 10];
    g_row[n] = excl;
    g_cur[n] = excl;
    g_inv[n] = 1.f / (float)max(d, 1);
}

// ---------------- K_fill: scatter edges into CSR slots ---------------------
__global__ void k_fill(const int* __restrict__ src, const int* __restrict__ dst) {
    int idx = blockIdx.x * blockDim.x + threadIdx.x;
    if (idx >= EE / 4) return;
    int4 s = reinterpret_cast<const int4*>(src)[idx];
    int4 d = reinterpret_cast<const int4*>(dst)[idx];
    int p0 = atomicAdd(&g_cur[d.x], 1); g_csr[p0] = s.x;
    int p1 = atomicAdd(&g_cur[d.y], 1); g_csr[p1] = s.y;
    int p2 = atomicAdd(&g_cur[d.z], 1); g_csr[p2] = s.z;
    int p3 = atomicAdd(&g_cur[d.w], 1); g_csr[p3] = s.w;
}

// ---------------- K2: proj  y1 = x@w1_l, z1 = x@w1_r  (f32x2 packed) -------
__global__ void k_proj(const float* __restrict__ x,
                       const float* __restrict__ w1l,
                       const float* __restrict__ w1r) {
    __shared__ float sw[DD * 32];
    __shared__ float sxT[32 * 132];

    const int tid = threadIdx.x;
    for (int i = tid; i < DD * 32; i += 256) {
        int k = i >> 5, j = i & 31;
        sw[i] = (j < 16) ? w1l[k * HH + j] : w1r[k * HH + (j - 16)];
    }

    const int row0 = blockIdx.x * 128;
    const int rq = tid >> 3;
    const int g  = tid & 7;

    u64 accp[2][4];   // row-pairs (rq*4+0,+1) and (rq*4+2,+3) x 4 outputs
#pragma unroll
    for (int i = 0; i < 2; i++)
#pragma unroll
        for (int j = 0; j < 4; j++) accp[i][j] = 0ull;

    const int rs = tid >> 3;
    const int q  = tid & 7;

    for (int kc = 0; kc < 4; kc++) {
        __syncthreads();
#pragma unroll
        for (int rr = rs; rr < 128; rr += 32) {
            int row = row0 + rr;
            float4 v = make_float4(0.f, 0.f, 0.f, 0.f);
            if (row < NN)
                v = reinterpret_cast<const float4*>(x + row * DD + kc * 32)[q];
            sxT[(q * 4 + 0) * 132 + rr] = v.x;
            sxT[(q * 4 + 1) * 132 + rr] = v.y;
            sxT[(q * 4 + 2) * 132 + rr] = v.z;
            sxT[(q * 4 + 3) * 132 + rr] = v.w;
        }
        __syncthreads();
#pragma unroll
        for (int kk = 0; kk < 32; kk++) {
            float4 xv = *reinterpret_cast<const float4*>(&sxT[kk * 132 + rq * 4]);
            float4 wv = *reinterpret_cast<const float4*>(&sw[(kc * 32 + kk) * 32 + g * 4]);
            u64 x01, x23, w0, w1, w2, w3;
            PK(x01, xv.x, xv.y);
            PK(x23, xv.z, xv.w);
            PK(w0, wv.x, wv.x);
            PK(w1, wv.y, wv.y);
            PK(w2, wv.z, wv.z);
            PK(w3, wv.w, wv.w);
            FMA2(accp[0][0], x01, w0); FMA2(accp[1][0], x23, w0);
            FMA2(accp[0][1], x01, w1); FMA2(accp[1][1], x23, w1);
            FMA2(accp[0][2], x01, w2); FMA2(accp[1][2], x23, w2);
            FMA2(accp[0][3], x01, w3); FMA2(accp[1][3], x23, w3);
        }
    }

    float acc[4][4];
#pragma unroll
    for (int j = 0; j < 4; j++) {
        UPK(acc[0][j], acc[1][j], accp[0][j]);
        UPK(acc[2][j], acc[3][j], accp[1][j]);
    }

#pragma unroll
    for (int i = 0; i < 4; i++) {
        int row = row0 + rq * 4 + i;
        if (row < NN) {
            float4 v = make_float4(acc[i][0], acc[i][1], acc[i][2], acc[i][3]);
            if (g < 4) reinterpret_cast<float4*>(g_y1 + row * HH)[g]     = v;
            else       reinterpret_cast<float4*>(g_z1 + row * HH)[g - 4] = v;
        }
    }
}

// ---------------- K6: collapse layer-2 weights against wc ------------------
__global__ void k_prep(const float* __restrict__ w2l, const float* __restrict__ w2r,
                       const float* __restrict__ b2,  const float* __restrict__ wc) {
    int t = threadIdx.x;
    if (t < 64) {
        int which = t >> 4, j = t & 15;
        const float* w = (which == 0 || which == 2) ? w2l : w2r;
        const float* c = (which < 2) ? wc : (wc + DD);
        float s = 0.f;
        for (int d = 0; d < DD; d++) s += w[j * DD + d] * c[d];
        g_u[which * 16 + j] = s;
    }
    if (t == 0) { float s = 0.f; for (int d = 0; d < DD; d++) s += b2[d] * wc[d];      g_u[64] = s; }
    if (t == 1) { float s = 0.f; for (int d = 0; d < DD; d++) s += b2[d] * wc[DD + d]; g_u[65] = s; }
}

// ---------------- K_gagg1: gather-aggregate y1 + fused h + contraction -----
// 4 threads per node; lane c handles components c*4..c*4+3 (one 64B line/quad)
__global__ void k_gagg1(const float* __restrict__ b1) {
    __shared__ float su[64];
    __shared__ float sb[16];
    int tid = threadIdx.x;
    if (tid < 64) su[tid] = g_u[tid];
    if (tid < 16) sb[tid] = b1[tid];
    __syncthreads();

    int t = blockIdx.x * 256 + tid;
    int n = t >> 2, c = t & 3;
    if (n >= NN) return;

    int beg = g_row[n], end = g_row[n + 1];
    float4 acc = make_float4(0.f, 0.f, 0.f, 0.f);
    for (int j = beg; j < end; j++) {
        int s = g_csr[j];
        float4 v = reinterpret_cast<const float4*>(g_y1 + (size_t)s * HH)[c];
        acc.x += v.x; acc.y += v.y; acc.z += v.z; acc.w += v.w;
    }

    float inv = g_inv[n];
    float4 z = reinterpret_cast<const float4*>(g_z1 + (size_t)n * HH)[c];
    int j0 = c * 4;
    float h0 = fmaxf(acc.x * inv + sb[j0 + 0] + z.x, 0.f);
    float h1 = fmaxf(acc.y * inv + sb[j0 + 1] + z.y, 0.f);
    float h2 = fmaxf(acc.z * inv + sb[j0 + 2] + z.z, 0.f);
    float h3 = fmaxf(acc.w * inv + sb[j0 + 3] + z.w, 0.f);

    float p1 = h0 * su[j0]      + h1 * su[j0 + 1]  + h2 * su[j0 + 2]  + h3 * su[j0 + 3];
    float q1 = h0 * su[16 + j0] + h1 * su[17 + j0] + h2 * su[18 + j0] + h3 * su[19 + j0];
    float p2 = h0 * su[32 + j0] + h1 * su[33 + j0] + h2 * su[34 + j0] + h3 * su[35 + j0];
    float q2 = h0 * su[48 + j0] + h1 * su[49 + j0] + h2 * su[50 + j0] + h3 * su[51 + j0];

    // quad reduction (warps are fully active: NN*4 is a multiple of 32)
    p1 += __shfl_xor_sync(FULL, p1, 1); p1 += __shfl_xor_sync(FULL, p1, 2);
    p2 += __shfl_xor_sync(FULL, p2, 1); p2 += __shfl_xor_sync(FULL, p2, 2);
    q1 += __shfl_xor_sync(FULL, q1, 1); q1 += __shfl_xor_sync(FULL, q1, 2);
    q2 += __shfl_xor_sync(FULL, q2, 1); q2 += __shfl_xor_sync(FULL, q2, 2);

    if (c == 0) {
        g_p[n] = make_float2(p1, p2);
        g_q[n] = make_float2(q1, q2);
    }
}

// ---------------- K_gagg2: gather-aggregate p + fused classifier scalars ---
__global__ void k_gagg2() {
    int n = blockIdx.x * blockDim.x + threadIdx.x;
    if (n >= NN) return;
    int beg = g_row[n], end = g_row[n + 1];
    float ax = 0.f, ay = 0.f;
    for (int j = beg; j < end; j++) {
        float2 v = g_p[g_csr[j]];
        ax += v.x; ay += v.y;
    }
    float inv = g_inv[n];
    float2 q = g_q[n];
    g_s1[n] = ax * inv + q.x + g_u[64];
    g_s2[n] = ay * inv + q.y + g_u[65];
}

// ---------------- K8: logits + partial BCE ---------------------------------
__global__ void k_loss(const int* __restrict__ a1, const int* __restrict__ a2,
                       const int* __restrict__ labels, const float* __restrict__ bc,
                       float* __restrict__ out) {
    int tid = threadIdx.x;
    float acc = 0.f;
    float bias = bc[0];
    for (int i = blockIdx.x * 256 + tid; i < BB; i += 64 * 256) {
        float l = g_s1[a1[i]] + g_s2[a2[i]] + bias;
        out[1 + i] = l;
        float y = (float)labels[i];
        acc += fmaxf(l, 0.f) - l * y + log1pf(expf(-fabsf(l)));
    }
    __shared__ float sred[256];
    sred[tid] = acc;
    __syncthreads();
    for (int s = 128; s > 0; s >>= 1) {
        if (tid < s) sred[tid] += sred[tid + s];
        __syncthreads();
    }
    if (tid == 0) g_partial[blockIdx.x] = sred[0];
}

// ---------------- K9: final loss reduce ------------------------------------
__global__ void k_final(float* __restrict__ out) {
    __shared__ float sred[64];
    int t = threadIdx.x;
    sred[t] = g_partial[t];
    __syncthreads();
    for (int s = 32; s > 0; s >>= 1) {
        if (t < s) sred[t] += sred[t + s];
        __syncthreads();
    }
    if (t == 0) out[0] = sred[0] * (1.f / (float)BB);
}

// ---------------- launch ----------------------------------------------------
extern "C" void kernel_launch(void* const* d_in, const int* in_sizes, int n_in,
                              void* d_out, int out_size) {
    const float* x    = (const float*)d_in[0];
    const float* w1l  = (const float*)d_in[1];
    const float* b1   = (const float*)d_in[2];
    const float* w1r  = (const float*)d_in[3];
    const float* w2l  = (const float*)d_in[4];
    const float* b2   = (const float*)d_in[5];
    const float* w2r  = (const float*)d_in[6];
    const float* wc   = (const float*)d_in[7];
    const float* bc   = (const float*)d_in[8];
    const int*   edge = (const int*)d_in[9];
    const int*   a1   = (const int*)d_in[10];
    const int*   a2   = (const int*)d_in[11];
    const int*   lab  = (const int*)d_in[12];
    float* out = (float*)d_out;

    const int* src = edge;
    const int* dst = edge + EE;

    k_zero <<<(NN + 1023) / 1024, 1024>>>();
    k_prep <<<1, 64>>>(w2l, w2r, b2, wc);
    k_deg  <<<(EE / 4 + 255) / 256, 256>>>(dst);
    k_scanA<<<98, 1024>>>();
    k_scanB<<<1, 128>>>();
    k_scanC<<<(NN + 255) / 256, 256>>>();
    k_proj <<<(NN + 127) / 128, 256>>>(x, w1l, w1r);
    k_fill <<<(EE / 4 + 255) / 256, 256>>>(src, dst);
    k_gagg1<<<(NN * 4 + 255) / 256, 256>>>(b1);
    k_gagg2<<<(NN + 255) / 256, 256>>>();
    k_loss <<<64, 256>>>(a1, a2, lab, bc, out);
    k_final<<<1, 64>>>(out);
}

// round 5
// speedup vs baseline: 1.5006x; 1.0756x over previous
#include <cuda_runtime.h>
#include <math.h>

#define NN 100000
#define DD 128
#define HH 16
#define EE 1600000
#define BB 16384
#define FULL 0xffffffffu
#define PROJ_BLOCKS ((NN + 127) / 128)      // 782
#define DEG_BLOCKS  ((EE / 4 + 255) / 256)  // 1563

typedef unsigned long long u64;

// ---------------- scratch (device globals) ---------------------------------
__device__ int    g_degi[NN];
__device__ int    g_incl[NN];
__device__ int    g_bsum[128];
__device__ int    g_boff[128];
__device__ int    g_row [NN + 1];
__device__ int    g_cur [NN];
__device__ float  g_inv [NN];
__device__ int    g_csr [EE];
__device__ float  g_y1  [NN * HH];
__device__ float  g_z1  [NN * HH];
__device__ float2 g_p   [NN];
__device__ float2 g_q   [NN];
__device__ float  g_s1  [NN];
__device__ float  g_s2  [NN];
__device__ float  g_u   [66];
__device__ float  g_partial[64];

// f32x2 packed math (sm_100+)
#define PK(d, lo, hi)  asm("mov.b64 %0, {%1,%2};" : "=l"(d) : "f"(lo), "f"(hi))
#define UPK(lo, hi, s) asm("mov.b64 {%0,%1}, %2;" : "=f"(lo), "=f"(hi) : "l"(s))
#define FMA2(d, a, b)  asm("fma.rn.f32x2 %0, %1, %2, %0;" : "+l"(d) : "l"(a), "l"(b))

// ---------------- K_init: zero degree counters + prep collapsed weights ----
__global__ void k_init(const float* __restrict__ w2l, const float* __restrict__ w2r,
                       const float* __restrict__ b2,  const float* __restrict__ wc) {
    if (blockIdx.x < 98) {
        int n = blockIdx.x * 1024 + threadIdx.x;
        if (n < NN) g_degi[n] = 0;
    } else {
        int t = threadIdx.x;
        if (t < 64) {
            int which = t >> 4, j = t & 15;
            const float* w = (which == 0 || which == 2) ? w2l : w2r;
            const float* c = (which < 2) ? wc : (wc + DD);
            float s = 0.f;
            for (int d = 0; d < DD; d++) s += w[j * DD + d] * c[d];
            g_u[which * 16 + j] = s;
        }
        if (t == 64) { float s = 0.f; for (int d = 0; d < DD; d++) s += b2[d] * wc[d];      g_u[64] = s; }
        if (t == 65) { float s = 0.f; for (int d = 0; d < DD; d++) s += b2[d] * wc[DD + d]; g_u[65] = s; }
    }
}

// ---------------- K_projdeg: proj GEMM blocks + degree-histogram blocks ----
__global__ void k_projdeg(const float* __restrict__ x,
                          const float* __restrict__ w1l,
                          const float* __restrict__ w1r,
                          const int*   __restrict__ dst) {
    __shared__ float sw[DD * 32];
    __shared__ float sxT[32 * 132];
    const int tid = threadIdx.x;

    if (blockIdx.x >= PROJ_BLOCKS) {
        // ---- degree histogram branch ----
        int idx = (blockIdx.x - PROJ_BLOCKS) * 256 + tid;
        if (idx < EE / 4) {
            int4 d = reinterpret_cast<const int4*>(dst)[idx];
            atomicAdd(&g_degi[d.x], 1);
            atomicAdd(&g_degi[d.y], 1);
            atomicAdd(&g_degi[d.z], 1);
            atomicAdd(&g_degi[d.w], 1);
        }
        return;
    }

    // ---- proj branch: y1 = x@w1_l, z1 = x@w1_r (f32x2 packed) ----
    for (int i = tid; i < DD * 32; i += 256) {
        int k = i >> 5, j = i & 31;
        sw[i] = (j < 16) ? w1l[k * HH + j] : w1r[k * HH + (j - 16)];
    }

    const int row0 = blockIdx.x * 128;
    const int rq = tid >> 3;
    const int g  = tid & 7;

    u64 accp[2][4];
#pragma unroll
    for (int i = 0; i < 2; i++)
#pragma unroll
        for (int j = 0; j < 4; j++) accp[i][j] = 0ull;

    const int rs = tid >> 3;
    const int q  = tid & 7;

    for (int kc = 0; kc < 4; kc++) {
        __syncthreads();
#pragma unroll
        for (int rr = rs; rr < 128; rr += 32) {
            int row = row0 + rr;
            float4 v = make_float4(0.f, 0.f, 0.f, 0.f);
            if (row < NN)
                v = reinterpret_cast<const float4*>(x + row * DD + kc * 32)[q];
            sxT[(q * 4 + 0) * 132 + rr] = v.x;
            sxT[(q * 4 + 1) * 132 + rr] = v.y;
            sxT[(q * 4 + 2) * 132 + rr] = v.z;
            sxT[(q * 4 + 3) * 132 + rr] = v.w;
        }
        __syncthreads();
#pragma unroll
        for (int kk = 0; kk < 32; kk++) {
            float4 xv = *reinterpret_cast<const float4*>(&sxT[kk * 132 + rq * 4]);
            float4 wv = *reinterpret_cast<const float4*>(&sw[(kc * 32 + kk) * 32 + g * 4]);
            u64 x01, x23, w0, w1, w2, w3;
            PK(x01, xv.x, xv.y);
            PK(x23, xv.z, xv.w);
            PK(w0, wv.x, wv.x);
            PK(w1, wv.y, wv.y);
            PK(w2, wv.z, wv.z);
            PK(w3, wv.w, wv.w);
            FMA2(accp[0][0], x01, w0); FMA2(accp[1][0], x23, w0);
            FMA2(accp[0][1], x01, w1); FMA2(accp[1][1], x23, w1);
            FMA2(accp[0][2], x01, w2); FMA2(accp[1][2], x23, w2);
            FMA2(accp[0][3], x01, w3); FMA2(accp[1][3], x23, w3);
        }
    }

    float acc[4][4];
#pragma unroll
    for (int j = 0; j < 4; j++) {
        UPK(acc[0][j], acc[1][j], accp[0][j]);
        UPK(acc[2][j], acc[3][j], accp[1][j]);
    }

#pragma unroll
    for (int i = 0; i < 4; i++) {
        int row = row0 + rq * 4 + i;
        if (row < NN) {
            float4 v = make_float4(acc[i][0], acc[i][1], acc[i][2], acc[i][3]);
            if (g < 4) reinterpret_cast<float4*>(g_y1 + row * HH)[g]     = v;
            else       reinterpret_cast<float4*>(g_z1 + row * HH)[g - 4] = v;
        }
    }
}

// ---------------- scan A: 1024-wide block inclusive scan -------------------
__global__ void k_scanA() {
    __shared__ int ws[32];
    int tid = threadIdx.x, lane = tid & 31, w = tid >> 5;
    int n = blockIdx.x * 1024 + tid;
    int v = (n < NN) ? g_degi[n] : 0;
    int x = v;
#pragma unroll
    for (int o = 1; o < 32; o <<= 1) {
        int t = __shfl_up_sync(FULL, x, o);
        if (lane >= o) x += t;
    }
    if (lane == 31) ws[w] = x;
    __syncthreads();
    if (w == 0) {
        int b = ws[lane];
#pragma unroll
        for (int o = 1; o < 32; o <<= 1) {
            int t = __shfl_up_sync(FULL, b, o);
            if (lane >= o) b += t;
        }
        ws[lane] = b;
    }
    __syncthreads();
    int incl = x + (w > 0 ? ws[w - 1] : 0);
    if (n < NN) g_incl[n] = incl;
    if (tid == 1023) g_bsum[blockIdx.x] = incl;
}

// ---------------- scan B: exclusive scan of block totals -------------------
__global__ void k_scanB() {
    __shared__ int s[128];
    int tid = threadIdx.x;
    int v = (tid < 98) ? g_bsum[tid] : 0;
    s[tid] = v;
    __syncthreads();
    for (int o = 1; o < 128; o <<= 1) {
        int t = (tid >= o) ? s[tid - o] : 0;
        __syncthreads();
        s[tid] += t;
        __syncthreads();
    }
    if (tid < 98) g_boff[tid] = s[tid] - v;
    if (tid == 0) g_row[NN] = EE;
}

// ---------------- scan C: finalize row offsets, cursors, inv-deg -----------
__global__ void k_scanC() {
    int n = blockIdx.x * blockDim.x + threadIdx.x;
    if (n >= NN) return;
    int d = g_degi[n];
    int excl = g_incl[n] - d + g_boff[n >> 10];
    g_row[n] = excl;
    g_cur[n] = excl;
    g_inv[n] = 1.f / (float)max(d, 1);
}

// ---------------- K_fill: scatter edges into CSR slots ---------------------
__global__ void k_fill(const int* __restrict__ src, const int* __restrict__ dst) {
    int idx = blockIdx.x * blockDim.x + threadIdx.x;
    if (idx >= EE / 4) return;
    int4 s = reinterpret_cast<const int4*>(src)[idx];
    int4 d = reinterpret_cast<const int4*>(dst)[idx];
    int p0 = atomicAdd(&g_cur[d.x], 1); g_csr[p0] = s.x;
    int p1 = atomicAdd(&g_cur[d.y], 1); g_csr[p1] = s.y;
    int p2 = atomicAdd(&g_cur[d.z], 1); g_csr[p2] = s.z;
    int p3 = atomicAdd(&g_cur[d.w], 1); g_csr[p3] = s.w;
}

// ---------------- K_gagg1: gather-aggregate y1 (MLP-4) + fused h + contract
// 4 threads per node; lane c handles components c*4..c*4+3
__global__ void k_gagg1(const float* __restrict__ b1) {
    __shared__ float su[64];
    __shared__ float sb[16];
    int tid = threadIdx.x;
    if (tid < 64) su[tid] = g_u[tid];
    if (tid < 16) sb[tid] = b1[tid];
    __syncthreads();

    int t = blockIdx.x * 256 + tid;
    int n = t >> 2, c = t & 3;
    if (n >= NN) return;

    int beg = g_row[n], end = g_row[n + 1];
    float4 acc = make_float4(0.f, 0.f, 0.f, 0.f);
    for (int j = beg; j < end; j += 4) {
        int last = end - 1;
        int j1 = min(j + 1, last), j2 = min(j + 2, last), j3 = min(j + 3, last);
        int s0 = g_csr[j], s1 = g_csr[j1], s2 = g_csr[j2], s3 = g_csr[j3];
        float w1 = (j + 1 < end) ? 1.f : 0.f;
        float w2 = (j + 2 < end) ? 1.f : 0.f;
        float w3 = (j + 3 < end) ? 1.f : 0.f;
        float4 v0 = reinterpret_cast<const float4*>(g_y1 + (size_t)s0 * HH)[c];
        float4 v1 = reinterpret_cast<const float4*>(g_y1 + (size_t)s1 * HH)[c];
        float4 v2 = reinterpret_cast<const float4*>(g_y1 + (size_t)s2 * HH)[c];
        float4 v3 = reinterpret_cast<const float4*>(g_y1 + (size_t)s3 * HH)[c];
        acc.x += v0.x + fmaf(w1, v1.x, fmaf(w2, v2.x, w3 * v3.x));
        acc.y += v0.y + fmaf(w1, v1.y, fmaf(w2, v2.y, w3 * v3.y));
        acc.z += v0.z + fmaf(w1, v1.z, fmaf(w2, v2.z, w3 * v3.z));
        acc.w += v0.w + fmaf(w1, v1.w, fmaf(w2, v2.w, w3 * v3.w));
    }

    float inv = g_inv[n];
    float4 z = reinterpret_cast<const float4*>(g_z1 + (size_t)n * HH)[c];
    int j0 = c * 4;
    float h0 = fmaxf(acc.x * inv + sb[j0 + 0] + z.x, 0.f);
    float h1 = fmaxf(acc.y * inv + sb[j0 + 1] + z.y, 0.f);
    float h2 = fmaxf(acc.z * inv + sb[j0 + 2] + z.z, 0.f);
    float h3 = fmaxf(acc.w * inv + sb[j0 + 3] + z.w, 0.f);

    float p1 = h0 * su[j0]      + h1 * su[j0 + 1]  + h2 * su[j0 + 2]  + h3 * su[j0 + 3];
    float q1 = h0 * su[16 + j0] + h1 * su[17 + j0] + h2 * su[18 + j0] + h3 * su[19 + j0];
    float p2 = h0 * su[32 + j0] + h1 * su[33 + j0] + h2 * su[34 + j0] + h3 * su[35 + j0];
    float q2 = h0 * su[48 + j0] + h1 * su[49 + j0] + h2 * su[50 + j0] + h3 * su[51 + j0];

    p1 += __shfl_xor_sync(FULL, p1, 1); p1 += __shfl_xor_sync(FULL, p1, 2);
    p2 += __shfl_xor_sync(FULL, p2, 1); p2 += __shfl_xor_sync(FULL, p2, 2);
    q1 += __shfl_xor_sync(FULL, q1, 1); q1 += __shfl_xor_sync(FULL, q1, 2);
    q2 += __shfl_xor_sync(FULL, q2, 1); q2 += __shfl_xor_sync(FULL, q2, 2);

    if (c == 0) {
        g_p[n] = make_float2(p1, p2);
        g_q[n] = make_float2(q1, q2);
    }
}

// ---------------- K_gagg2: gather-aggregate p (MLP-4) + classifier scalars -
__global__ void k_gagg2() {
    int n = blockIdx.x * blockDim.x + threadIdx.x;
    if (n >= NN) return;
    int beg = g_row[n], end = g_row[n + 1];
    float ax = 0.f, ay = 0.f;
    for (int j = beg; j < end; j += 4) {
        int last = end - 1;
        int j1 = min(j + 1, last), j2 = min(j + 2, last), j3 = min(j + 3, last);
        int s0 = g_csr[j], s1 = g_csr[j1], s2 = g_csr[j2], s3 = g_csr[j3];
        float w1 = (j + 1 < end) ? 1.f : 0.f;
        float w2 = (j + 2 < end) ? 1.f : 0.f;
        float w3 = (j + 3 < end) ? 1.f : 0.f;
        float2 v0 = g_p[s0], v1 = g_p[s1], v2 = g_p[s2], v3 = g_p[s3];
        ax += v0.x + fmaf(w1, v1.x, fmaf(w2, v2.x, w3 * v3.x));
        ay += v0.y + fmaf(w1, v1.y, fmaf(w2, v2.y, w3 * v3.y));
    }
    float inv = g_inv[n];
    float2 q = g_q[n];
    g_s1[n] = ax * inv + q.x + g_u[64];
    g_s2[n] = ay * inv + q.y + g_u[65];
}

// ---------------- K8: logits + partial BCE ---------------------------------
__global__ void k_loss(const int* __restrict__ a1, const int* __restrict__ a2,
                       const int* __restrict__ labels, const float* __restrict__ bc,
                       float* __restrict__ out) {
    int tid = threadIdx.x;
    float acc = 0.f;
    float bias = bc[0];
    for (int i = blockIdx.x * 256 + tid; i < BB; i += 64 * 256) {
        float l = g_s1[a1[i]] + g_s2[a2[i]] + bias;
        out[1 + i] = l;
        float y = (float)labels[i];
        acc += fmaxf(l, 0.f) - l * y + log1pf(expf(-fabsf(l)));
    }
    __shared__ float sred[256];
    sred[tid] = acc;
    __syncthreads();
    for (int s = 128; s > 0; s >>= 1) {
        if (tid < s) sred[tid] += sred[tid + s];
        __syncthreads();
    }
    if (tid == 0) g_partial[blockIdx.x] = sred[0];
}

// ---------------- K9: final loss reduce ------------------------------------
__global__ void k_final(float* __restrict__ out) {
    __shared__ float sred[64];
    int t = threadIdx.x;
    sred[t] = g_partial[t];
    __syncthreads();
    for (int s = 32; s > 0; s >>= 1) {
        if (t < s) sred[t] += sred[t + s];
        __syncthreads();
    }
    if (t == 0) out[0] = sred[0] * (1.f / (float)BB);
}

// ---------------- launch ----------------------------------------------------
extern "C" void kernel_launch(void* const* d_in, const int* in_sizes, int n_in,
                              void* d_out, int out_size) {
    const float* x    = (const float*)d_in[0];
    const float* w1l  = (const float*)d_in[1];
    const float* b1   = (const float*)d_in[2];
    const float* w1r  = (const float*)d_in[3];
    const float* w2l  = (const float*)d_in[4];
    const float* b2   = (const float*)d_in[5];
    const float* w2r  = (const float*)d_in[6];
    const float* wc   = (const float*)d_in[7];
    const float* bc   = (const float*)d_in[8];
    const int*   edge = (const int*)d_in[9];
    const int*   a1   = (const int*)d_in[10];
    const int*   a2   = (const int*)d_in[11];
    const int*   lab  = (const int*)d_in[12];
    float* out = (float*)d_out;

    const int* src = edge;
    const int* dst = edge + EE;

    k_init   <<<99, 1024>>>(w2l, w2r, b2, wc);
    k_projdeg<<<PROJ_BLOCKS + DEG_BLOCKS, 256>>>(x, w1l, w1r, dst);
    k_scanA  <<<98, 1024>>>();
    k_scanB  <<<1, 128>>>();
    k_scanC  <<<(NN + 255) / 256, 256>>>();
    k_fill   <<<(EE / 4 + 255) / 256, 256>>>(src, dst);
    k_gagg1  <<<(NN * 4 + 255) / 256, 256>>>(b1);
    k_gagg2  <<<(NN + 255) / 256, 256>>>();
    k_loss   <<<64, 256>>>(a1, a2, lab, bc, out);
    k_final  <<<1, 64>>>(out);
}